// round 1
// baseline (speedup 1.0000x reference)
#include <cuda_runtime.h>
#include <math.h>

#define CH 128
#define E_CAP 4
#define WARPS 8
#define ROWS_PER_BLOCK 64   // 8 warps x 8 rows each

// Reparameterization constants (match reference, fp64 -> fp32 rounding)
#define PED_F         1.4551915228366852e-11f   // 2^-36, exact in fp32
#define GAMMA_BOUND_F 3.814697265625e-06f       // 2^-18, exact in fp32
#define BETA_BOUND_F  1.0000072759311444e-03f   // sqrt(1e-6 + 2^-36)

// Static device scratch (no allocations allowed)
__device__ float g_b[CH];
__device__ int   g_cnt[CH];
__device__ int   g_eidx[CH * CH];
__device__ float g_eval[CH * CH];

// ---------------------------------------------------------------------------
// Prepass: compute b[i] and the sparse rows of g (exact reference arithmetic).
// One warp per output channel. Entries kept in ascending-j order.
// ---------------------------------------------------------------------------
__global__ void gdn_prepass(const float* __restrict__ beta,
                            const float* __restrict__ gamma) {
    int w    = threadIdx.x >> 5;
    int lane = threadIdx.x & 31;
    int row  = blockIdx.x * (blockDim.x >> 5) + w;
    if (row >= CH) return;

    if (lane == 0) {
        float bb = fmaxf(beta[row], BETA_BOUND_F);
        g_b[row] = bb * bb - PED_F;
    }

    // coalesced float4 load: lane l covers j = 4l..4l+3
    float4 g4 = ((const float4*)(gamma + (long long)row * CH))[lane];
    float gin[4] = {g4.x, g4.y, g4.z, g4.w};

    float vals[4];
    int   idxs[4];
    int m = 0;
#pragma unroll
    for (int k = 0; k < 4; ++k) {
        float g = fmaxf(gin[k], GAMMA_BOUND_F);
        g = g * g - PED_F;
        if (g != 0.0f) {
            vals[m] = g;
            idxs[m] = lane * 4 + k;
            m++;
        }
    }

    // inclusive warp scan of m -> exclusive offset
    int off = m;
#pragma unroll
    for (int d = 1; d < 32; d <<= 1) {
        int o = __shfl_up_sync(0xffffffffu, off, d);
        if (lane >= d) off += o;
    }
    int total = __shfl_sync(0xffffffffu, off, 31);
    off -= m;

    for (int t = 0; t < m; ++t) {
        g_eidx[row * CH + off + t] = idxs[t];
        g_eval[row * CH + off + t] = vals[t];
    }
    if (lane == 31) g_cnt[row] = total;
}

// ---------------------------------------------------------------------------
// Main kernel: streaming sparse GDN. Memory-bound design:
//   - float4 loads of x, row staged in smem (conflict-free STS.128)
//   - lane l owns channels {l, l+32, l+64, l+96}: bank-conflict-free gather,
//     coalesced STG.32 stores
//   - first sparse entry register-cached; overflow entries from smem / L2
// ---------------------------------------------------------------------------
__global__ void __launch_bounds__(256)
gdn_main(const float* __restrict__ x, float* __restrict__ out, int nrows) {
    __shared__ float sb[CH];
    __shared__ int   scnt[CH];
    __shared__ int   seidx[CH * E_CAP];
    __shared__ float seval[CH * E_CAP];
    __shared__ float sx[WARPS][CH];

    int tid = threadIdx.x;

    if (tid < CH) {
        sb[tid]   = g_b[tid];
        scnt[tid] = g_cnt[tid];
    }
    for (int t = tid; t < CH * E_CAP; t += blockDim.x) {
        int c = t / E_CAP;
        int e = t % E_CAP;
        seidx[t] = g_eidx[c * CH + e];
        seval[t] = g_eval[c * CH + e];
    }
    __syncthreads();

    int w    = tid >> 5;
    int lane = tid & 31;
    float* sxw = &sx[w][0];

    // register-cache per-lane channel params (4 channels per lane)
    float myb[4];
    int   mycnt[4];
    int   myi0[4];
    float myv0[4];
#pragma unroll
    for (int k = 0; k < 4; ++k) {
        int c     = lane + 32 * k;
        myb[k]    = sb[c];
        mycnt[k]  = scnt[c];
        myi0[k]   = seidx[c * E_CAP];
        myv0[k]   = seval[c * E_CAP];
    }

    int rowbase = blockIdx.x * ROWS_PER_BLOCK;

#pragma unroll
    for (int i = 0; i < ROWS_PER_BLOCK / WARPS; ++i) {
        int row = rowbase + i * WARPS + w;
        if (row >= nrows) break;

        const float4 xv = ((const float4*)x)[(long long)row * (CH / 4) + lane];

        __syncwarp();                       // protect prior iteration's reads
        ((float4*)sxw)[lane] = xv;
        __syncwarp();

#pragma unroll
        for (int k = 0; k < 4; ++k) {
            int   c   = lane + 32 * k;
            float acc = myb[k];
            int   cnt = mycnt[k];
            if (cnt > 0) {
                float t = sxw[myi0[k]];
                float s = t * t;
                acc = fmaf(myv0[k], s, acc);
            }
            for (int e = 1; e < cnt; ++e) {
                int   idx;
                float val;
                if (e < E_CAP) {
                    idx = seidx[c * E_CAP + e];
                    val = seval[c * E_CAP + e];
                } else {
                    idx = g_eidx[c * CH + e];
                    val = g_eval[c * CH + e];
                }
                float t = sxw[idx];
                float s = t * t;
                acc = fmaf(val, s, acc);
            }
            float xc = sxw[c];
            out[(long long)row * CH + c] = xc * rsqrtf(acc);
        }
    }
}

// ---------------------------------------------------------------------------
extern "C" void kernel_launch(void* const* d_in, const int* in_sizes, int n_in,
                              void* d_out, int out_size) {
    const float* x     = (const float*)d_in[0];
    const float* beta  = (const float*)d_in[1];
    const float* gamma = (const float*)d_in[2];
    float*       out   = (float*)d_out;

    int nrows = in_sizes[0] / CH;

    gdn_prepass<<<16, 256>>>(beta, gamma);

    int blocks = (nrows + ROWS_PER_BLOCK - 1) / ROWS_PER_BLOCK;
    gdn_main<<<blocks, 256>>>(x, out, nrows);
}

// round 2
// speedup vs baseline: 1.1450x; 1.1450x over previous
#include <cuda_runtime.h>
#include <math.h>

#define CH 128
#define CH4 (CH / 4)

// Reparameterization constants (match reference, fp64 -> fp32 rounding)
#define PED_F         1.4551915228366852e-11f   // 2^-36, exact in fp32
#define GAMMA_BOUND_F 3.814697265625e-06f       // 2^-18, exact in fp32
#define BETA_BOUND_F  1.0000072759311444e-03f   // sqrt(1e-6 + 2^-36)

// Static device scratch (no allocations allowed)
__device__ float g_b[CH];
__device__ float g_dv[CH];          // diagonal value per channel (valid if g_diag_ok)
__device__ int   g_diag_ok;         // 1 if g is exactly diagonal (sparse-compacted)
__device__ int   g_cnt[CH];
__device__ int   g_eidx[CH * CH];
__device__ float g_eval[CH * CH];

// ---------------------------------------------------------------------------
// Prepass: compute b[i], sparse rows of g (exact reference arithmetic), the
// per-channel diagonal value, and a single "is diagonal" flag.
// One block of 128 warps-worth of work: warp per channel (4 blocks of 32 warps
// is overkill; use 16 blocks x 8 warps as before).
// ---------------------------------------------------------------------------
__global__ void gdn_prepass(const float* __restrict__ beta,
                            const float* __restrict__ gamma) {
    int w    = threadIdx.x >> 5;
    int lane = threadIdx.x & 31;
    int row  = blockIdx.x * (blockDim.x >> 5) + w;
    if (row >= CH) return;

    if (lane == 0) {
        float bb = fmaxf(beta[row], BETA_BOUND_F);
        g_b[row] = bb * bb - PED_F;
    }

    float4 g4 = ((const float4*)(gamma + (long long)row * CH))[lane];
    float gin[4] = {g4.x, g4.y, g4.z, g4.w};

    float vals[4];
    int   idxs[4];
    int m = 0;
#pragma unroll
    for (int k = 0; k < 4; ++k) {
        float g = fmaxf(gin[k], GAMMA_BOUND_F);
        g = g * g - PED_F;
        if (g != 0.0f) {
            vals[m] = g;
            idxs[m] = lane * 4 + k;
            m++;
        }
    }

    // exclusive warp scan of m
    int off = m;
#pragma unroll
    for (int d = 1; d < 32; d <<= 1) {
        int o = __shfl_up_sync(0xffffffffu, off, d);
        if (lane >= d) off += o;
    }
    int total = __shfl_sync(0xffffffffu, off, 31);
    off -= m;

    for (int t = 0; t < m; ++t) {
        g_eidx[row * CH + off + t] = idxs[t];
        g_eval[row * CH + off + t] = vals[t];
    }
    if (lane == 31) g_cnt[row] = total;
}

// Tiny follow-up: set g_dv + g_diag_ok (single block, deterministic).
__global__ void gdn_flag() {
    __shared__ int ok;
    if (threadIdx.x == 0) ok = 1;
    __syncthreads();
    int c = threadIdx.x;             // 128 threads
    int cnt = g_cnt[c];
    int idx = g_eidx[c * CH];
    float v = g_eval[c * CH];
    bool diag = (cnt == 1) && (idx == c);
    g_dv[c] = diag ? v : 0.0f;
    if (!diag) atomicAnd(&ok, 0);
    __syncthreads();
    if (threadIdx.x == 0) g_diag_ok = ok;
}

// ---------------------------------------------------------------------------
// Main kernel. Fast path (g diagonal): pure elementwise float4 stream, no
// shared memory, no sync, register-cached per-channel params. Fallback
// (general sparse g): per-element gather from L2-hot x row + entry tables.
// ---------------------------------------------------------------------------
__global__ void __launch_bounds__(256)
gdn_main(const float* __restrict__ x, float* __restrict__ out, long long n4) {
    const long long stride = (long long)gridDim.x * blockDim.x;   // multiple of 32
    long long i = (long long)blockIdx.x * blockDim.x + threadIdx.x;

    // fixed channel-group for this thread (stride % 32 == 0)
    const int c4 = (int)(i & (CH4 - 1));
    const int c0 = c4 * 4;

    const float4* __restrict__ x4   = (const float4*)x;
    float4* __restrict__       out4 = (float4*)out;

    if (g_diag_ok) {
        const float4 b4 = ((const float4*)g_b)[c4];
        const float4 v4 = ((const float4*)g_dv)[c4];

        // 2-way software pipeline for extra MLP
        for (; i + stride < n4; i += 2 * stride) {
            float4 xa = x4[i];
            float4 xb = x4[i + stride];
            float4 oa, ob;
            oa.x = xa.x * rsqrtf(fmaf(v4.x, xa.x * xa.x, b4.x));
            oa.y = xa.y * rsqrtf(fmaf(v4.y, xa.y * xa.y, b4.y));
            oa.z = xa.z * rsqrtf(fmaf(v4.z, xa.z * xa.z, b4.z));
            oa.w = xa.w * rsqrtf(fmaf(v4.w, xa.w * xa.w, b4.w));
            ob.x = xb.x * rsqrtf(fmaf(v4.x, xb.x * xb.x, b4.x));
            ob.y = xb.y * rsqrtf(fmaf(v4.y, xb.y * xb.y, b4.y));
            ob.z = xb.z * rsqrtf(fmaf(v4.z, xb.z * xb.z, b4.z));
            ob.w = xb.w * rsqrtf(fmaf(v4.w, xb.w * xb.w, b4.w));
            out4[i] = oa;
            out4[i + stride] = ob;
        }
        if (i < n4) {
            float4 xa = x4[i];
            float4 oa;
            oa.x = xa.x * rsqrtf(fmaf(v4.x, xa.x * xa.x, b4.x));
            oa.y = xa.y * rsqrtf(fmaf(v4.y, xa.y * xa.y, b4.y));
            oa.z = xa.z * rsqrtf(fmaf(v4.z, xa.z * xa.z, b4.z));
            oa.w = xa.w * rsqrtf(fmaf(v4.w, xa.w * xa.w, b4.w));
            out4[i] = oa;
        }
    } else {
        // General sparse fallback (correct for any g); x row re-read from L2.
        for (; i < n4; i += stride) {
            long long row  = i >> 5;              // / CH4
            const float* xr = x + row * CH;
            float4 o;
            float r[4];
#pragma unroll
            for (int k = 0; k < 4; ++k) {
                int   c   = c0 + k;
                float acc = g_b[c];
                int   cnt = g_cnt[c];
                for (int e = 0; e < cnt; ++e) {
                    float t = xr[g_eidx[c * CH + e]];
                    acc = fmaf(g_eval[c * CH + e], t * t, acc);
                }
                r[k] = xr[c] * rsqrtf(acc);
            }
            o.x = r[0]; o.y = r[1]; o.z = r[2]; o.w = r[3];
            out4[i] = o;
        }
    }
}

// ---------------------------------------------------------------------------
extern "C" void kernel_launch(void* const* d_in, const int* in_sizes, int n_in,
                              void* d_out, int out_size) {
    const float* x     = (const float*)d_in[0];
    const float* beta  = (const float*)d_in[1];
    const float* gamma = (const float*)d_in[2];
    float*       out   = (float*)d_out;

    long long nelem = (long long)in_sizes[0];
    long long n4    = nelem / 4;

    gdn_prepass<<<16, 256>>>(beta, gamma);
    gdn_flag<<<1, 128>>>();

    // 148 SMs x 8 blocks of 256 threads = full occupancy wave
    int blocks = 148 * 8;
    gdn_main<<<blocks, 256>>>(x, out, n4);
}